// round 16
// baseline (speedup 1.0000x reference)
#include <cuda_runtime.h>
#include <math.h>

#define NS_   6
#define NT_   4
#define B_    2
#define N_    32
#define H_    768
#define W_    768
#define ROI_  28
#define C_    10           // NS + NT
#define L_    39           // 1 + NS + N
#define NEGV  (-100.0f)

#define SEAM_TOT (B_ * H_ * W_)                 // 1179648
#define FULL_OUT (SEAM_TOT + 2 * B_ * L_ + B_)  // 1179806
#define LUTN  (NS_ + N_)                        // 38
#define HW_   (H_ * W_)

// Scratch: zero-initialized at module load; k_post re-zeroes hist/cstuff after
// consuming them, so every graph replay starts clean (self-cleaning pipeline).
__device__ int g_hist[B_ * N_ * C_];
__device__ int g_cstuff[B_ * NS_];
__device__ __align__(16) unsigned char g_pp[B_ * H_ * W_];
__device__ float g_lutf[B_ * LUTN];

// XLA logistic_expander form: 1 / (1 + exp(-x)). sigmoid(-100) == 0 exactly.
__device__ __forceinline__ float jsig(float x) {
    return __fdiv_rn(1.0f, __fadd_rn(1.0f, expf(-x)));
}

// warp-aggregated shared-hist add: uniform fast path, match_any fallback
__device__ __forceinline__ void hist_add(int key, int lane,
                                         int* sh_hist, int* sh_cst) {
    const unsigned FULL = 0xffffffffu;
    int k0 = __shfl_sync(FULL, key, 0);
    if (__all_sync(FULL, key == k0)) {
        if (lane == 0) {
            if (k0 >= 64) atomicAdd(&sh_hist[k0 - 64], 32);
            else          atomicAdd(&sh_cst[k0], 32);
        }
    } else {
        unsigned mm = __match_any_sync(FULL, key);
        if (lane == __ffs(mm) - 1) {
            int cnt = __popc(mm);
            if (key >= 64) atomicAdd(&sh_hist[key - 64], cnt);
            else           atomicAdd(&sh_cst[key], cnt);
        }
    }
}

// ---- kernel 1: fused per-pixel argmax + histograms -------------------------
// One block per (row, batch); 256 thr x 3 px; 7 blocks/SM. All 10 channel
// loads are FRONT-BATCHED per tile (MLP=10, one DRAM round-trip) — the fast
// path consumes only s0..s5 (separate scoreboard slot for s6..s9, so it never
// waits on them), the slow path no longer pays a second serialized DRAM wait.
// Row-active instances compacted; y-interpolated 28-float mask rows
// precomputed into shared memory (exact ref op order). Per-warp 32-px-window
// ballot filter; tree argmax (first-max); hybrid warp-aggregated histograms.
__global__ void __launch_bounds__(256, 7)
k_main(const float* __restrict__ sem, const float* __restrict__ roi,
       const float* __restrict__ bbx, const int* __restrict__ cls) {
    const unsigned FULL = 0xffffffffu;
    const int y = blockIdx.x;
    const int b = blockIdx.y;
    const int t = threadIdx.x;
    const int lane = t & 31;

    __shared__ int sh_hist[N_ * C_];
    __shared__ int sh_cst[NS_];
    __shared__ int sh_K;
    __shared__ int sa_n[N_], sa_x0[N_], sa_x1r[N_], sa_xs[N_], sa_xe[N_];
    __shared__ int sa_inYm[N_], sa_cls[N_], sa_r0[N_], sa_r1[N_];
    __shared__ float sa_wy[N_], sa_rx[N_];
    __shared__ float sh_my[N_][ROI_];       // y-interpolated mask rows

    for (int i = t; i < N_ * C_; i += 256) sh_hist[i] = 0;
    if (t < NS_) sh_cst[t] = 0;

    if (t < 32) {
        const float* bb = bbx + (b * N_ + t) * 4;
        float y0f = bb[0], x0f = bb[1], y1f = bb[2], x1f = bb[3];
        int y0 = (int)floorf(y0f), x0 = (int)floorf(x0f);
        int y1 = (int)floorf(y1f), x1 = (int)floorf(x1f);
        int y1r = (int)(rintf(y1f) + 1.0f);   // round-half-even like jnp.round
        int x1r = (int)(rintf(x1f) + 1.0f);
        int hi = y1 - y0 + 1; if (hi < 1) hi = 1;
        int wi = x1 - x0 + 1; if (wi < 1) wi = 1;
        int ys = max(y0, 0), ye = min(y1 + 1, H_);
        float ry = __fdiv_rn(28.0f, (float)hi);
        float rx = __fdiv_rn(28.0f, (float)wi);
        int c = cls[b * N_ + t];
        int mskoff = ((b * N_ + t) * NT_ + c) * ROI_ * ROI_;

        bool inYs = (y >= y0) && (y < y1r);
        unsigned mask = __ballot_sync(FULL, inYs);
        if (t == 0) sh_K = __popc(mask);
        if (inYs) {
            int slot = __popc(mask & ((1u << t) - 1u));
            sa_n[slot] = t;
            sa_x0[slot] = x0; sa_x1r[slot] = x1r;
            sa_xs[slot] = max(x0, 0); sa_xe[slot] = min(x1 + 1, W_);
            sa_cls[slot] = c; sa_rx[slot] = rx;
            int inYm = (y >= ys) && (y < ye);
            sa_inYm[slot] = inYm;
            if (inYm) {
                float sy = __fsub_rn(
                    __fmul_rn(__fadd_rn(__fsub_rn((float)y, (float)y0), 0.5f), ry),
                    0.5f);
                sy = fminf(fmaxf(sy, 0.0f), 27.0f);
                float fiy0 = floorf(sy);
                int iy0 = (int)fiy0;
                int iy1 = min(iy0 + 1, ROI_ - 1);
                sa_wy[slot] = __fsub_rn(sy, fiy0);
                sa_r0[slot] = mskoff + iy0 * ROI_;
                sa_r1[slot] = mskoff + iy1 * ROI_;
            } else {
                sa_wy[slot] = 0.0f; sa_r0[slot] = 0; sa_r1[slot] = 0;
            }
        }
    }
    __syncthreads();

    const int K = sh_K;

    // precompute y-interpolated mask rows (exact ref order: m0*(1-wy)+m1*wy)
    for (int idx = t; idx < K * ROI_; idx += 256) {
        int slot = idx / ROI_, col = idx - slot * ROI_;
        if (sa_inYm[slot]) {
            float m0 = __ldg(roi + sa_r0[slot] + col);
            float m1 = __ldg(roi + sa_r1[slot] + col);
            float wy = sa_wy[slot];
            sh_my[slot][col] = __fadd_rn(__fmul_rn(m0, __fsub_rn(1.0f, wy)),
                                         __fmul_rn(m1, wy));
        }
    }
    __syncthreads();

    const float C_OUT = -0.0f;
    const float* semb0 = sem + (size_t)b * (C_ * HW_) + (size_t)y * W_;

    for (int px = 0; px < W_ / 256; px++) {
        const int x = t + px * 256;

        // warp filter: instances whose strict x-interval meets this warp's
        // 32-pixel window
        unsigned wmask;
        {
            int wlo = px * 256 + (t & ~31);
            bool inter = false;
            if (lane < K) inter = (sa_x0[lane] <= wlo + 31) && (sa_x1r[lane] > wlo);
            wmask = __ballot_sync(FULL, inter);
        }

        // ALL 10 channel loads front-batched (one DRAM round-trip, MLP=10).
        // Fast path consumes only s0..s5 — s6..s9 get their own scoreboard
        // slot and are waited on only in the slow branch.
        float s0 = __ldg(semb0 + 0 * (size_t)HW_ + x);
        float s1 = __ldg(semb0 + 1 * (size_t)HW_ + x);
        float s2 = __ldg(semb0 + 2 * (size_t)HW_ + x);
        float s3 = __ldg(semb0 + 3 * (size_t)HW_ + x);
        float s4 = __ldg(semb0 + 4 * (size_t)HW_ + x);
        float s5 = __ldg(semb0 + 5 * (size_t)HW_ + x);
        float s6 = __ldg(semb0 + 6 * (size_t)HW_ + x);
        float s7 = __ldg(semb0 + 7 * (size_t)HW_ + x);
        float s8 = __ldg(semb0 + 8 * (size_t)HW_ + x);
        float s9 = __ldg(semb0 + 9 * (size_t)HW_ + x);

        // tree argmax over stuff (first-max: right wins on strict >)
        int   i01 = (s1 > s0) ? 1 : 0;       float v01 = (s1 > s0) ? s1 : s0;
        int   i23 = (s3 > s2) ? 3 : 2;       float v23 = (s3 > s2) ? s3 : s2;
        int   i45 = (s5 > s4) ? 5 : 4;       float v45 = (s5 > s4) ? s5 : s4;
        int   i03 = (v23 > v01) ? i23 : i01; float v03 = (v23 > v01) ? v23 : v01;
        int   bi  = (v45 > v03) ? i45 : i03; float best = (v45 > v03) ? v45 : v03;

        // FAST PATH: no instance window here and C_OUT can't win anywhere
        bool slow = (wmask != 0) || __any_sync(FULL, best < 0.0f);
        if (!slow) {
            g_pp[((size_t)b * H_ + y) * W_ + x] = (unsigned char)bi;
            hist_add(bi, lane, sh_hist, sh_cst);
            continue;
        }

        // sem argmax extension over thing channels (already in flight)
        int   i67 = (s7 > s6) ? 7 : 6;       float v67 = (s7 > s6) ? s7 : s6;
        int   i89 = (s9 > s8) ? 9 : 8;       float v89 = (s9 > s8) ? s9 : s8;
        int   i69 = (v89 > v67) ? i89 : i67; float v69 = (v89 > v67) ? v89 : v67;
        int   sem_pred = (v69 > best) ? i69 : bi;

        int nextn = 0;
        for (unsigned mrem = wmask; mrem; mrem &= mrem - 1) {
            int k = __ffs(mrem) - 1;
            int n = sa_n[k];
            if (n > nextn && best < 0.0f) { best = C_OUT; bi = NS_ + nextn; }
            nextn = n + 1;

            float v;
            bool sxin = (x >= sa_x0[k]) && (x < sa_x1r[k]);
            if (!sxin) {
                v = C_OUT;
            } else {
                int ck = sa_cls[k];
                float a = (ck == 0) ? s6 : (ck == 1) ? s7 : (ck == 2) ? s8 : s9;
                float m;
                bool mxin = sa_inYm[k] && (x >= sa_xs[k]) && (x < sa_xe[k]);
                if (mxin) {
                    float sx = __fsub_rn(
                        __fmul_rn(__fadd_rn(__fsub_rn((float)x, (float)sa_x0[k]), 0.5f),
                                  sa_rx[k]),
                        0.5f);
                    sx = fminf(fmaxf(sx, 0.0f), 27.0f);
                    float fix0 = floorf(sx);
                    int ix0 = (int)fix0;
                    int ix1 = min(ix0 + 1, ROI_ - 1);
                    float wx = __fsub_rn(sx, fix0);
                    float c0 = sh_my[k][ix0];
                    float c1 = sh_my[k][ix1];
                    float omx = __fsub_rn(1.0f, wx);
                    m = __fadd_rn(__fmul_rn(c0, omx), __fmul_rn(c1, wx));
                } else {
                    m = NEGV;
                }
                v = __fmul_rn(__fadd_rn(jsig(a), jsig(m)), __fadd_rn(a, m));
            }
            if (v > best) { best = v; bi = NS_ + n; }
        }
        if (nextn < N_ && best < 0.0f) { best = C_OUT; bi = NS_ + nextn; }

        g_pp[((size_t)b * H_ + y) * W_ + x] = (unsigned char)bi;

        int key = (bi >= NS_) ? (64 + (bi - NS_) * C_ + sem_pred) : bi;
        hist_add(key, lane, sh_hist, sh_cst);
    }
    __syncthreads();

    for (int i = t; i < N_ * C_; i += 256) {
        int v = sh_hist[i];
        if (v) atomicAdd(&g_hist[b * N_ * C_ + i], v);
    }
    if (t < NS_) {
        int v = sh_cst[t];
        if (v) atomicAdd(&g_cstuff[b * NS_ + t], v);
    }
}

// ---- kernel 2: warp-parallel relabel + small outputs; self-cleans scratch --
__global__ void __launch_bounds__(64)
k_post(const int* __restrict__ cls, float* __restrict__ out, int out_size) {
    const unsigned FULL = 0xffffffffu;
    int b = threadIdx.x >> 5;
    int lane = threadIdx.x & 31;
    int* hist = g_hist + (b * N_ + lane) * C_;

    int tot = 0, mc = 0, smax = 0;
#pragma unroll
    for (int c = 0; c < C_; c++) {
        int h = hist[c];
        tot += h;
        if (h > mc) { mc = h; smax = c; }
    }
    int pres = (tot > 0);
    int tmp = cls[b * N_ + lane] + NS_;
    int br1 = (smax == tmp);
    int br2 = (!br1) && (2 * mc >= tot) && (smax < NS_) && pres;
    int semlab = br2 ? smax : tmp;
    int kept = pres && !br2;

    int sp[NS_];
#pragma unroll
    for (int c = 0; c < NS_; c++) {
        int v = (semlab == c) ? tot : 0;
#pragma unroll
        for (int off = 16; off; off >>= 1) v += __shfl_down_sync(FULL, v, off);
        v = __shfl_sync(FULL, v, 0);
        sp[c] = g_cstuff[b * NS_ + c] + v;
    }

    int srank[NS_], nst = 0;
#pragma unroll
    for (int c = 0; c < NS_; c++) { if (sp[c] > 0) nst++; srank[c] = nst - 1; }

    unsigned kb = __ballot_sync(FULL, kept);
    int rank_k = __popc(kb & ((1u << lane) - 1u));
    int rk = __popc(kb);

    float* lut = g_lutf + b * LUTN;
    if (lane < NS_) lut[lane] = (float)(srank[lane] + 1);
    int lv = kept ? (1 + nst + rank_k)
                  : ((semlab < NS_) ? (srank[semlab] + 1) : 0);
    lut[NS_ + lane] = (float)lv;

    if (out_size >= FULL_OUT) {
        float* pcls = out + SEAM_TOT + b * L_;
        float* pisc = out + SEAM_TOT + B_ * L_ + b * L_;
        pcls[lane] = -1.0f;
        if (lane < L_ - 32) pcls[32 + lane] = -1.0f;
        __syncwarp(FULL);
        if (lane == 0) pcls[0] = 255.0f;
        if (lane < NS_ && sp[lane] > 0) pcls[1 + srank[lane]] = (float)lane;
        if (kept) pcls[1 + nst + rank_k] = (float)tmp;
        int vl = 1 + nst + rk;
        pisc[lane] = (lane < vl) ? 0.0f : -1.0f;
        if (lane < L_ - 32) pisc[32 + lane] = ((32 + lane) < vl) ? 0.0f : -1.0f;
        if (lane == 0) out[SEAM_TOT + 2 * B_ * L_ + b] = (float)vl;
    }
    // zero any residual output beyond the defined region (usually empty loop)
    for (int i = FULL_OUT + threadIdx.x; i < out_size; i += 64) out[i] = 0.0f;

    // self-clean scratch for the next graph replay
#pragma unroll
    for (int c = 0; c < C_; c++) hist[c] = 0;
    if (lane < NS_) g_cstuff[b * NS_ + lane] = 0;
}

// ---- kernel 3: LUT remap; shared LUT, 1 quad/thread, 1152 blocks -----------
__global__ void __launch_bounds__(256)
k_out(float* __restrict__ out) {
    __shared__ float lut[B_ * LUTN];
    int t = threadIdx.x;
    if (t < B_ * LUTN) lut[t] = g_lutf[t];
    __syncthreads();
    int i = blockIdx.x * 256 + t;              // quad index
    const int HWQ = HW_ / 4;
    unsigned int p = ((const unsigned int*)g_pp)[i];
    const float* l = lut + ((i >= HWQ) ? LUTN : 0);
    float4 o;
    o.x = l[p & 0xFF];
    o.y = l[(p >> 8) & 0xFF];
    o.z = l[(p >> 16) & 0xFF];
    o.w = l[(p >> 24) & 0xFF];
    ((float4*)out)[i] = o;
}

extern "C" void kernel_launch(void* const* d_in, const int* in_sizes, int n_in,
                              void* d_out, int out_size) {
    const float* sem = nullptr;
    const float* roi = nullptr;
    const float* bbx = nullptr;
    const int*   cls = nullptr;
    for (int i = 0; i < n_in; i++) {
        long long s = in_sizes[i];
        if (s >= 4000000)                 sem = (const float*)d_in[i];
        else if (s >= 100000)             roi = (const float*)d_in[i];
        else if (s >= 512 && s <= 4096)   bbx = (const float*)d_in[i];
        else if (s == 256) { if (!bbx) bbx = (const float*)d_in[i]; }
        else if (s <= 255)                cls = (const int*)d_in[i];
    }
    if (!sem) sem = (const float*)d_in[0];
    if (!roi) roi = (const float*)d_in[1];
    if (!bbx) bbx = (const float*)d_in[2];
    if (!cls) cls = (const int*)d_in[3];

    float* out = (float*)d_out;

    dim3 g1(H_, B_);
    k_main<<<g1, 256>>>(sem, roi, bbx, cls);
    k_post<<<1, 64>>>(cls, out, out_size);
    k_out<<<SEAM_TOT / 4 / 256, 256>>>(out);   // 1152 blocks
}